// round 9
// baseline (speedup 1.0000x reference)
#include <cuda_runtime.h>
#include <cuda_bf16.h>
#include <cstdint>

typedef unsigned long long ull;

#define NTHREADS 256
#define MARGIN   1e-3f
#define QCAP     2048

// ---------------- smem layout (bytes) ----------------
#define X_OFF    0          // fp32 x [d][r] 64*128*4          = 32768
#define A_OFF    32768      // bf16 A [128 r][136] (272B pitch) = 34816
#define B_OFF    67584      // bf16 B [512 k][136] (272B pitch) = 139264 (later aliased as q_s)
#define T1_OFF   206848     // 128*4
#define T2_OFF   207360     // 512*4
#define AMIN_OFF 209408     // [2][128] f32
#define KEY_OFF  210432     // ull [128]
#define IND_OFF  211456     // int [128]
#define LRED_OFF 211968     // double [8]
#define QN_OFF   212032     // int (+pad)
#define QBUF_OFF 212048     // int [QCAP] = 8192
#define SMEM_BYTES 220256

__device__ double   g_loss_sum = 0.0;
__device__ unsigned g_ticket   = 0;

__device__ __forceinline__ uint32_t smem_u32(const void* p) {
    uint32_t a;
    asm("{ .reg .u64 t; cvta.to.shared.u64 t, %1; cvt.u32.u64 %0, t; }" : "=r"(a) : "l"(p));
    return a;
}
__device__ __forceinline__ void ldsm4(uint32_t* r, uint32_t addr) {
    asm volatile("ldmatrix.sync.aligned.m8n8.x4.shared.b16 {%0,%1,%2,%3}, [%4];"
        : "=r"(r[0]), "=r"(r[1]), "=r"(r[2]), "=r"(r[3]) : "r"(addr));
}
__device__ __forceinline__ void mma_bf16(float* c, const uint32_t* a, uint32_t b0, uint32_t b1) {
    asm volatile("mma.sync.aligned.m16n8k16.row.col.f32.bf16.bf16.f32 "
        "{%0,%1,%2,%3}, {%4,%5,%6,%7}, {%8,%9}, {%0,%1,%2,%3};"
        : "+f"(c[0]), "+f"(c[1]), "+f"(c[2]), "+f"(c[3])
        : "r"(a[0]), "r"(a[1]), "r"(a[2]), "r"(a[3]), "r"(b0), "r"(b1));
}
__device__ __forceinline__ uint32_t bfp(float a, float b) {
    __nv_bfloat162 t = __floats2bfloat162_rn(a, b);   // .x = a (low half), .y = b
    return *(uint32_t*)&t;
}

// Exact distance recheck — byte-identical to the proven rel_err=0.0 scalar chain:
// m via sequential fmaf over d ascending, dist = fl( fl(t1 + t2) - 2*m ).
__device__ __forceinline__ void exact_check(int r, int k, const float* __restrict__ emb,
                                            const float* x_s, const float* t1_s,
                                            const float* t2_s, ull* key_s) {
    const float4* p4 = (const float4*)(emb + (size_t)k * 64);
    float m = 0.0f;
    #pragma unroll 1
    for (int t = 0; t < 16; ++t) {
        float4 v = __ldg(p4 + t);
        m = fmaf(x_s[((4 * t + 0) << 7) + r], v.x, m);
        m = fmaf(x_s[((4 * t + 1) << 7) + r], v.y, m);
        m = fmaf(x_s[((4 * t + 2) << 7) + r], v.z, m);
        m = fmaf(x_s[((4 * t + 3) << 7) + r], v.w, m);
    }
    float dist = __fsub_rn(__fadd_rn(t1_s[r], t2_s[k]), 2.0f * m);
    ull u = ((ull)__float_as_uint(dist) << 32) | (unsigned)k;
    atomicMin(key_s + r, u);                    // min dist, ties -> min k
}

__global__ __launch_bounds__(NTHREADS, 1)
void vq_main_kernel(const float* __restrict__ lat,
                    const float* __restrict__ emb,
                    float* __restrict__ out,
                    long long numel, long long loss_idx, int grid_n)
{
    extern __shared__ unsigned char smem[];
    const uint32_t smem_base = smem_u32(smem);
    float*  x_s    = (float*)(smem + X_OFF);      // [d][r]
    float*  t1_s   = (float*)(smem + T1_OFF);
    float*  t2_s   = (float*)(smem + T2_OFF);
    float*  amin_s = (float*)(smem + AMIN_OFF);   // [2][128]
    ull*    key_s  = (ull*)(smem + KEY_OFF);      // [128]
    int*    ind_s  = (int*)(smem + IND_OFF);
    double* lred   = (double*)(smem + LRED_OFF);
    int*    qn_s   = (int*)(smem + QN_OFF);
    int*    qbuf   = (int*)(smem + QBUF_OFF);

    const int tid  = threadIdx.x;
    const int wid  = tid >> 5;
    const int lane = tid & 31;
    const int n0   = blockIdx.x * 128;
    const int b    = n0 >> 12;
    const int p0   = n0 & 4095;
    const float* xg = lat + ((size_t)b << 18) + p0;

    if (tid == 0) *qn_s = 0;
    if (tid < 128) key_s[tid] = ~0ull;

    // ---- load x: fp32 + bf16 hi/lo into A = [x_hi(64) | x_lo(64)], 272B pitch ----
    for (int i = tid; i < 64 * 128; i += NTHREADS) {
        int d = i >> 7, r = i & 127;
        float v = __ldg(&xg[(d << 12) + r]);
        x_s[i] = v;
        __nv_bfloat16 h = __float2bfloat16(v);
        float hf = __bfloat162float(h);
        __nv_bfloat16 l = __float2bfloat16(v - hf);
        *(__nv_bfloat16*)(smem + A_OFF + r * 272 + d * 2)       = h;
        *(__nv_bfloat16*)(smem + A_OFF + r * 272 + 128 + d * 2) = l;
    }
    // ---- load e: bf16 hi duplicated into B = [e_hi(64) | e_hi(64)], 272B pitch ----
    for (int i = tid; i < 512 * 16; i += NTHREADS) {
        int k = i >> 4, d4 = i & 15;
        float4 v = __ldg((const float4*)emb + i);
        uint2 uu = make_uint2(bfp(v.x, v.y), bfp(v.z, v.w));
        *(uint2*)(smem + B_OFF + k * 272 + d4 * 8)       = uu;
        *(uint2*)(smem + B_OFF + k * 272 + 128 + d4 * 8) = uu;
    }
    __syncthreads();

    // ---- A fragments: warp = (rowgroup, code-half); cached across both passes ----
    const int g  = lane >> 2, tq = lane & 3;
    const int R0 = (wid >> 1) * 32;
    const int C0 = (wid & 1) * 256;
    const int lrow = lane & 15, lsel = lane >> 4;

    uint32_t aF[2][8][4];
    #pragma unroll
    for (int mi = 0; mi < 2; ++mi)
        #pragma unroll
        for (int ks = 0; ks < 8; ++ks)
            ldsm4(aF[mi][ks],
                  smem_base + A_OFF + (R0 + 16 * mi + lrow) * 272 + ks * 32 + lsel * 16);

    // ---- t1[r]: sequential fp32 chain over d (EXACT, replicates reference) ----
    if (tid < 128) {
        float acc = 0.0f;
        #pragma unroll 1
        for (int d = 0; d < 64; ++d) {
            float v = x_s[(d << 7) + tid];
            acc = __fadd_rn(acc, __fmul_rn(v, v));
        }
        t1_s[tid] = acc;
    }
    // ---- t2[k]: sequential fp32 chain over d (EXACT) ----
    for (int k = tid; k < 512; k += NTHREADS) {
        const float4* p4 = (const float4*)(emb + (size_t)k * 64);
        float acc = 0.0f;
        #pragma unroll 1
        for (int t = 0; t < 16; ++t) {
            float4 v = __ldg(p4 + t);
            acc = __fadd_rn(acc, __fmul_rn(v.x, v.x));
            acc = __fadd_rn(acc, __fmul_rn(v.y, v.y));
            acc = __fadd_rn(acc, __fmul_rn(v.z, v.z));
            acc = __fadd_rn(acc, __fmul_rn(v.w, v.w));
        }
        t2_s[k] = acc;
    }
    __syncthreads();

    // ================= PASS 1: approx min of s = t2[k] - 2*m_hat =================
    float rmin[4] = {3.4e38f, 3.4e38f, 3.4e38f, 3.4e38f};
    #pragma unroll 1
    for (int c4 = 0; c4 < 4; ++c4) {
        float acc[2][8][4];
        #pragma unroll
        for (int mi = 0; mi < 2; ++mi)
            #pragma unroll
            for (int nj = 0; nj < 8; ++nj)
                #pragma unroll
                for (int q = 0; q < 4; ++q) acc[mi][nj][q] = 0.0f;

        #pragma unroll
        for (int ks = 0; ks < 8; ++ks) {
            uint32_t bF[4][4];
            #pragma unroll
            for (int nb = 0; nb < 4; ++nb)
                ldsm4(bF[nb], smem_base + B_OFF +
                      (C0 + c4 * 64 + nb * 16 + lrow) * 272 + ks * 32 + lsel * 16);
            #pragma unroll
            for (int mi = 0; mi < 2; ++mi)
                #pragma unroll
                for (int nb = 0; nb < 4; ++nb) {
                    mma_bf16(acc[mi][2 * nb],     aF[mi][ks], bF[nb][0], bF[nb][2]);
                    mma_bf16(acc[mi][2 * nb + 1], aF[mi][ks], bF[nb][1], bF[nb][3]);
                }
        }
        #pragma unroll
        for (int nj = 0; nj < 8; ++nj) {
            int k0 = C0 + c4 * 64 + nj * 8 + 2 * tq;
            float2 t2v = *(const float2*)(t2_s + k0);
            #pragma unroll
            for (int mi = 0; mi < 2; ++mi) {
                float* a = acc[mi][nj];
                rmin[2*mi]   = fminf(rmin[2*mi],
                                     fminf(t2v.x - 2.0f*a[0], t2v.y - 2.0f*a[1]));
                rmin[2*mi+1] = fminf(rmin[2*mi+1],
                                     fminf(t2v.x - 2.0f*a[2], t2v.y - 2.0f*a[3]));
            }
        }
    }
    #pragma unroll
    for (int j = 0; j < 4; ++j) {
        float v = rmin[j];
        v = fminf(v, __shfl_xor_sync(0xffffffffu, v, 1));
        v = fminf(v, __shfl_xor_sync(0xffffffffu, v, 2));
        if (tq == 0)
            amin_s[(wid & 1) * 128 + R0 + 16 * (j >> 1) + 8 * (j & 1) + g] = v;
    }
    __syncthreads();

    float thr[4];
    #pragma unroll
    for (int j = 0; j < 4; ++j) {
        int row = R0 + 16 * (j >> 1) + 8 * (j & 1) + g;
        thr[j] = fminf(amin_s[row], amin_s[128 + row]) + MARGIN;
    }

    // ================= PASS 2: enumerate ALL candidates s < thr =================
    #pragma unroll 1
    for (int c4 = 0; c4 < 4; ++c4) {
        float acc[2][8][4];
        #pragma unroll
        for (int mi = 0; mi < 2; ++mi)
            #pragma unroll
            for (int nj = 0; nj < 8; ++nj)
                #pragma unroll
                for (int q = 0; q < 4; ++q) acc[mi][nj][q] = 0.0f;

        #pragma unroll
        for (int ks = 0; ks < 8; ++ks) {
            uint32_t bF[4][4];
            #pragma unroll
            for (int nb = 0; nb < 4; ++nb)
                ldsm4(bF[nb], smem_base + B_OFF +
                      (C0 + c4 * 64 + nb * 16 + lrow) * 272 + ks * 32 + lsel * 16);
            #pragma unroll
            for (int mi = 0; mi < 2; ++mi)
                #pragma unroll
                for (int nb = 0; nb < 4; ++nb) {
                    mma_bf16(acc[mi][2 * nb],     aF[mi][ks], bF[nb][0], bF[nb][2]);
                    mma_bf16(acc[mi][2 * nb + 1], aF[mi][ks], bF[nb][1], bF[nb][3]);
                }
        }
        #pragma unroll
        for (int nj = 0; nj < 8; ++nj) {
            int k0 = C0 + c4 * 64 + nj * 8 + 2 * tq;
            float2 t2v = *(const float2*)(t2_s + k0);
            #pragma unroll
            for (int mi = 0; mi < 2; ++mi) {
                float* a = acc[mi][nj];
                int rlo = R0 + 16 * mi + g, rhi = rlo + 8;
                float s00 = t2v.x - 2.0f * a[0], s01 = t2v.y - 2.0f * a[1];
                float s10 = t2v.x - 2.0f * a[2], s11 = t2v.y - 2.0f * a[3];
                if (s00 < thr[2*mi]) {
                    int slot = atomicAdd(qn_s, 1);
                    if (slot < QCAP) qbuf[slot] = (rlo << 16) | k0;
                    else exact_check(rlo, k0, emb, x_s, t1_s, t2_s, key_s);
                }
                if (s01 < thr[2*mi]) {
                    int slot = atomicAdd(qn_s, 1);
                    if (slot < QCAP) qbuf[slot] = (rlo << 16) | (k0 + 1);
                    else exact_check(rlo, k0 + 1, emb, x_s, t1_s, t2_s, key_s);
                }
                if (s10 < thr[2*mi+1]) {
                    int slot = atomicAdd(qn_s, 1);
                    if (slot < QCAP) qbuf[slot] = (rhi << 16) | k0;
                    else exact_check(rhi, k0, emb, x_s, t1_s, t2_s, key_s);
                }
                if (s11 < thr[2*mi+1]) {
                    int slot = atomicAdd(qn_s, 1);
                    if (slot < QCAP) qbuf[slot] = (rhi << 16) | (k0 + 1);
                    else exact_check(rhi, k0 + 1, emb, x_s, t1_s, t2_s, key_s);
                }
            }
        }
    }
    __syncthreads();

    // ---- cooperative exact recheck of queued candidates ----
    {
        int nq = *qn_s; if (nq > QCAP) nq = QCAP;
        for (int q = tid; q < nq; q += NTHREADS) {
            int ent = qbuf[q];
            exact_check(ent >> 16, ent & 0xffff, emb, x_s, t1_s, t2_s, key_s);
        }
    }
    __syncthreads();
    if (tid < 128) ind_s[tid] = (int)(key_s[tid] & 0xffffffffu);
    __syncthreads();

    // ---- gather selected codes into q_s [128][65] (aliases B region) ----
    float* q_s = (float*)(smem + B_OFF);
    for (int i = tid; i < 128 * 64; i += NTHREADS) {
        int rr = i >> 6, d = i & 63;
        q_s[rr * 65 + d] = __ldg(&emb[(size_t)ind_s[rr] * 64 + d]);
    }
    __syncthreads();

    // ---- straight-through output + loss partial (proven path) ----
    float lsum = 0.0f;
    const size_t obase = ((size_t)b << 18) + p0;
    for (int i = tid; i < 64 * 128; i += NTHREADS) {
        int d = i >> 7, rr = i & 127;
        float e = q_s[rr * 65 + d];
        float x = x_s[(d << 7) + rr];
        float qm = __fsub_rn(e, x);                             // fl(q - lat)
        out[obase + ((size_t)d << 12) + rr] = __fadd_rn(x, qm); // fl(lat + fl(q-lat))
        lsum = fmaf(qm, qm, lsum);
    }
    #pragma unroll
    for (int off = 16; off > 0; off >>= 1)
        lsum += __shfl_xor_sync(0xffffffffu, lsum, off);
    if (lane == 0) lred[wid] = (double)lsum;
    __syncthreads();

    if (tid == 0) {
        double s = 0.0;
        #pragma unroll
        for (int w = 0; w < NTHREADS / 32; ++w) s += lred[w];
        atomicAdd(&g_loss_sum, s);
        __threadfence();
        unsigned ticket = atomicAdd(&g_ticket, 1u);
        if (ticket == (unsigned)(grid_n - 1)) {
            double tot = atomicAdd(&g_loss_sum, 0.0);
            float lm = (float)(tot / (double)numel);
            out[loss_idx] = __fadd_rn(__fmul_rn(lm, 0.25f), lm);
            g_loss_sum = 0.0;
            g_ticket   = 0;
            __threadfence();
        }
    }
}

extern "C" void kernel_launch(void* const* d_in, const int* in_sizes, int n_in,
                              void* d_out, int out_size)
{
    const float* lat = (const float*)d_in[0];
    const float* emb = (const float*)d_in[1];
    float* out = (float*)d_out;

    const long long numel = (long long)in_sizes[0];     // 8388608
    const int n_rows = (int)(numel / 64);               // 131072
    const int grid   = n_rows / 128;                    // 1024

    cudaFuncSetAttribute(vq_main_kernel,
                         cudaFuncAttributeMaxDynamicSharedMemorySize, SMEM_BYTES);

    long long loss_idx = (out_size > numel) ? numel : (long long)out_size - 1;
    vq_main_kernel<<<grid, NTHREADS, SMEM_BYTES>>>(lat, emb, out,
                                                   numel, loss_idx, grid);
}